// round 3
// baseline (speedup 1.0000x reference)
#include <cuda_runtime.h>
#include <cstdint>

#define N_NODES 100000
#define N_EDGES 1600000
#define D 32
#define SCAN_BLK 1024
#define N_SCAN_BLOCKS ((N_NODES + SCAN_BLK - 1) / SCAN_BLK)   // 98

// Allocation-free scratch
__device__ int g_cnt[N_NODES];        // per-dst degree
__device__ int g_offs[N_NODES];       // exclusive scan of cnt (stable)
__device__ int g_offs2[N_NODES];      // running copy consumed by scatter
__device__ int g_bsum[N_SCAN_BLOCKS];
__device__ int g_bscan[N_SCAN_BLOCKS];
__device__ int g_sorted[N_EDGES];     // src ids grouped by dst

// ---------------------------------------------------------------------------
__global__ void zero_cnt() {
    int i = blockIdx.x * blockDim.x + threadIdx.x;
    if (i < N_NODES) g_cnt[i] = 0;
}

// Pass A: count degrees. 4 edges/thread via int4; return-less atomicAdd -> REDG.
__global__ void __launch_bounds__(256) pass_count(const int4* __restrict__ dst4) {
    int t = blockIdx.x * blockDim.x + threadIdx.x;
    if (t >= N_EDGES / 4) return;
    int4 d = dst4[t];
    atomicAdd(&g_cnt[d.x], 1);
    atomicAdd(&g_cnt[d.y], 1);
    atomicAdd(&g_cnt[d.z], 1);
    atomicAdd(&g_cnt[d.w], 1);
}

// Scan stage 1: block-local exclusive scan
__global__ void __launch_bounds__(SCAN_BLK) scan1() {
    __shared__ int sh[SCAN_BLK];
    int tid = threadIdx.x;
    int gid = blockIdx.x * SCAN_BLK + tid;
    int v = (gid < N_NODES) ? g_cnt[gid] : 0;
    sh[tid] = v;
    __syncthreads();
#pragma unroll
    for (int off = 1; off < SCAN_BLK; off <<= 1) {
        int t = 0;
        if (tid >= off) t = sh[tid - off];
        __syncthreads();
        if (tid >= off) sh[tid] += t;
        __syncthreads();
    }
    if (gid < N_NODES) g_offs[gid] = sh[tid] - v;
    if (tid == SCAN_BLK - 1) g_bsum[blockIdx.x] = sh[tid];
}

// Scan stage 2: scan of block sums
__global__ void scan2() {
    __shared__ int sh[128];
    int tid = threadIdx.x;
    int v = (tid < N_SCAN_BLOCKS) ? g_bsum[tid] : 0;
    sh[tid] = v;
    __syncthreads();
#pragma unroll
    for (int off = 1; off < 128; off <<= 1) {
        int t = 0;
        if (tid >= off) t = sh[tid - off];
        __syncthreads();
        if (tid >= off) sh[tid] += t;
        __syncthreads();
    }
    if (tid < N_SCAN_BLOCKS) g_bscan[tid] = sh[tid] - v;
}

// Scan stage 3: finalize offsets; also produce the working copy for scatter.
__global__ void __launch_bounds__(SCAN_BLK) scan3() {
    int gid = blockIdx.x * SCAN_BLK + threadIdx.x;
    if (gid < N_NODES) {
        int o = g_offs[gid] + g_bscan[blockIdx.x];
        g_offs[gid]  = o;
        g_offs2[gid] = o;
    }
}

// Pass B: rank + scatter fused. 4 edges/thread via int4.
__global__ void __launch_bounds__(256) pass_scatter(const int4* __restrict__ src4,
                                                    const int4* __restrict__ dst4) {
    int t = blockIdx.x * blockDim.x + threadIdx.x;
    if (t >= N_EDGES / 4) return;
    int4 s = src4[t];
    int4 d = dst4[t];
    int p0 = atomicAdd(&g_offs2[d.x], 1);
    int p1 = atomicAdd(&g_offs2[d.y], 1);
    int p2 = atomicAdd(&g_offs2[d.z], 1);
    int p3 = atomicAdd(&g_offs2[d.w], 1);
    g_sorted[p0] = s.x;
    g_sorted[p1] = s.y;
    g_sorted[p2] = s.z;
    g_sorted[p3] = s.w;
}

// Pass C: fused segment-mean + GraphSAGE combine. One warp per dst node.
__global__ void __launch_bounds__(256) aggregate_combine(
    const float* __restrict__ feat,
    const float* __restrict__ W_self,
    const float* __restrict__ W_neigh,
    const float* __restrict__ b_neigh,
    float* __restrict__ out)
{
    const int lane = threadIdx.x & 31;
    const int warp = (blockIdx.x * blockDim.x + threadIdx.x) >> 5;
    const int n_warps = (gridDim.x * blockDim.x) >> 5;

    float ws[D], wn[D];
#pragma unroll
    for (int i = 0; i < D; ++i) {
        ws[i] = W_self[lane * D + i];
        wn[i] = W_neigh[lane * D + i];
    }
    const float bias = b_neigh[lane];

    for (int n = warp; n < N_NODES; n += n_warps) {
        const int start = g_offs[n];
        const int cnt   = g_cnt[n];

        float acc0 = 0.f, acc1 = 0.f;
        for (int base = 0; base < cnt; base += 32) {
            const int m = min(cnt - base, 32);
            const int sv = (lane < m) ? g_sorted[start + base + lane] : 0;
#pragma unroll
            for (int i = 0; i < 32; i += 8) {
                if (i >= m) break;
                float a[8];
#pragma unroll
                for (int j = 0; j < 8; ++j) {
                    int s = __shfl_sync(0xffffffffu, sv, i + j);
                    a[j] = (i + j < m) ? __ldg(&feat[s * D + lane]) : 0.f;
                }
#pragma unroll
                for (int j = 0; j < 8; j += 2) { acc0 += a[j]; acc1 += a[j + 1]; }
            }
        }
        const float acc = acc0 + acc1;

        const float inv = 1.0f / fmaxf((float)cnt, 1.0f);
        const float nb  = acc * inv;
        const float f   = feat[n * D + lane];

        float o = bias;
#pragma unroll
        for (int i = 0; i < D; ++i) {
            o += __shfl_sync(0xffffffffu, f,  i) * ws[i];
            o += __shfl_sync(0xffffffffu, nb, i) * wn[i];
        }
        out[n * D + lane] = o;
    }
}

// ---------------------------------------------------------------------------
// inputs: feat, W_self, W_neigh, b_neigh, src, dst
extern "C" void kernel_launch(void* const* d_in, const int* in_sizes, int n_in,
                              void* d_out, int out_size)
{
    const float* feat    = (const float*)d_in[0];
    const float* W_self  = (const float*)d_in[1];
    const float* W_neigh = (const float*)d_in[2];
    const float* b_neigh = (const float*)d_in[3];
    const int*   src     = (const int*)d_in[4];
    const int*   dst     = (const int*)d_in[5];
    float* out = (float*)d_out;

    zero_cnt<<<(N_NODES + 255) / 256, 256>>>();
    pass_count<<<(N_EDGES / 4 + 255) / 256, 256>>>((const int4*)dst);
    scan1<<<N_SCAN_BLOCKS, SCAN_BLK>>>();
    scan2<<<1, 128>>>();
    scan3<<<N_SCAN_BLOCKS, SCAN_BLK>>>();
    pass_scatter<<<(N_EDGES / 4 + 255) / 256, 256>>>((const int4*)src, (const int4*)dst);
    aggregate_combine<<<1184, 256>>>(feat, W_self, W_neigh, b_neigh, out);
}